// round 2
// baseline (speedup 1.0000x reference)
#include <cuda_runtime.h>

// Problem constants (fixed by setup_inputs: B=8,T=4096,D=1024,A=32,S=16,TTL=64)
#define NB_B 8
#define NB_T 4096
#define NB_D 1024
#define NB_A 32
#define SP   16
#define HH   256          // H = max(ttl*4, span*4) = 256
#define WW   (HH - SP + 1) // 241
#define NT   256          // threads per block
#define NPAIR (NB_B * NB_A)

// alias table (index -> root or -1)
__constant__ signed char c_alias[64] = {
  -1,-1,-1,-1,-1,-1,-1,-1,-1,-1,-1,   // 0-10
  11,-1,11,-1,-1,11,                  // 11-16
  -1,-1,-1,-1,                        // 17-20
  21,21,21,                           // 21-23
  -1,-1,-1,-1,-1,-1,-1,               // 24-30
  31,31,31,                           // 31-33
  -1,-1,-1,-1,-1,-1,-1,               // 34-40
  41,41,41,41,                        // 41-44
  -1,-1,-1,-1,-1,-1,                  // 45-50
  51,51,51,                           // 51-53
  -1,-1,-1,-1,-1,-1,-1,-1,-1,-1      // 54-63
};

__global__ void __launch_bounds__(NT, 2) cm_kernel(
    const float* __restrict__ hidden,
    const float* __restrict__ anchor,
    const int*   __restrict__ ids,
    const int*   __restrict__ aend,
    float*       __restrict__ out)
{
  const int p    = blockIdx.x;        // p = b*A + a
  const int b    = p / NB_A;
  const int tid  = threadIdx.x;
  const int lane = tid & 31;
  const int wp   = tid >> 5;          // 8 warps

  __shared__ float part[8][8];        // per-chunk row partials [row][warp]
  __shared__ float sred[48];          // generic reduction scratch
  __shared__ int   ftok[HH];
  __shared__ int   sp_[SP];
  __shared__ signed char s_alias[64];
  __shared__ int   s_root, s_has, s_atok;
  __shared__ float s_invden;
  __shared__ unsigned long long s_spanmask, s_cmask;
  __shared__ float s_shift, s_dot, s_nf2, s_nr2;

  const int ae    = aend[p];
  const int start = ae + 1;

  if (tid < 64) s_alias[tid] = c_alias[tid];
  ftok[tid] = ids[b * NB_T + start + tid];
  if (tid < SP) sp_[tid] = ids[b * NB_T + ae - (SP - 1) + tid];
  if (tid == 0) s_atok = ids[b * NB_T + ae];

  // each thread owns 4 consecutive columns: d = 4*tid .. 4*tid+3
  const float4 a4 = reinterpret_cast<const float4*>(anchor)[(size_t)p * (NB_D / 4) + tid];
  const float4* hb = reinterpret_cast<const float4*>(hidden)
                     + ((size_t)b * NB_T + start) * (NB_D / 4);

  float4 cs = make_float4(0.f, 0.f, 0.f, 0.f);  // column sums over H rows
  float shift_acc = 0.f;                         // valid on tid<8

  // ---- streaming pass over the 256x1024 future block (1 MB) ----
  for (int c = 0; c < HH; c += 8) {
    float4 x[8];
#pragma unroll
    for (int r = 0; r < 8; r++)
      x[r] = hb[(size_t)(c + r) * (NB_D / 4) + tid];
#pragma unroll
    for (int r = 0; r < 8; r++) {
      cs.x += x[r].x; cs.y += x[r].y; cs.z += x[r].z; cs.w += x[r].w;
      float dx = x[r].x - a4.x, dy = x[r].y - a4.y;
      float dz = x[r].z - a4.z, dw = x[r].w - a4.w;
      float v = dx * dx + dy * dy + dz * dz + dw * dw;
#pragma unroll
      for (int o = 16; o; o >>= 1) v += __shfl_xor_sync(0xffffffffu, v, o);
      if (lane == 0) part[r][wp] = v;
    }
    __syncthreads();
    if (tid < 8) {
      float s = 0.f;
#pragma unroll
      for (int k = 0; k < 8; k++) s += part[tid][k];
      shift_acc += sqrtf(s);
    }
    __syncthreads();
  }

  // ---- block reductions: shift, dot(a,colsum), |colsum|^2, |a|^2 ----
  if (tid < 8) sred[tid] = shift_acc;
  float dot = a4.x * cs.x + a4.y * cs.y + a4.z * cs.z + a4.w * cs.w;
  float nf2 = cs.x * cs.x + cs.y * cs.y + cs.z * cs.z + cs.w * cs.w;
  float nr2 = a4.x * a4.x + a4.y * a4.y + a4.z * a4.z + a4.w * a4.w;
#pragma unroll
  for (int o = 16; o; o >>= 1) {
    dot += __shfl_xor_sync(0xffffffffu, dot, o);
    nf2 += __shfl_xor_sync(0xffffffffu, nf2, o);
    nr2 += __shfl_xor_sync(0xffffffffu, nr2, o);
  }
  if (lane == 0) { sred[8 + wp] = dot; sred[16 + wp] = nf2; sred[24 + wp] = nr2; }
  __syncthreads();

  if (tid == 0) {
    float sh = 0.f, d = 0.f, f = 0.f, r2 = 0.f;
    for (int k = 0; k < 8; k++) {
      sh += sred[k]; d += sred[8 + k]; f += sred[16 + k]; r2 += sred[24 + k];
    }
    s_shift = sh * (1.f / HH);
    s_dot = d; s_nf2 = f; s_nr2 = r2;

    // root / span analysis (scalar, once per block)
    int root = -1;
    for (int s = 0; s < SP; s++) {
      int al = s_alias[sp_[s]];
      if (al >= 0) { root = al; break; }
    }
    if (root < 0) {
      int counts[SP]; int maxc = 0;
      for (int s = 0; s < SP; s++) {
        int c2 = 0;
        for (int s2 = 0; s2 < SP; s2++) c2 += (sp_[s2] == sp_[s]);
        counts[s] = c2; if (c2 > maxc) maxc = c2;
      }
      int mode = 64;
      for (int s = 0; s < SP; s++)
        if (counts[s] == maxc && sp_[s] < mode) mode = sp_[s];
      root = mode;
    }
    unsigned long long smask = 0ull; int den = 0;
    for (int s = 0; s < SP; s++) {
      bool first = true;
      for (int s2 = 0; s2 < s; s2++)
        if (sp_[s2] == sp_[s]) { first = false; break; }
      if (first) { den++; smask |= (1ull << sp_[s]); }
    }
    s_root = root;
    s_spanmask = smask;
    s_invden = 1.f / (float)den;
    s_has = (root == 11 || root == 21 || root == 31 || root == 41 || root == 51) ? 1 : 0;
    unsigned long long cm = 0ull;
    switch (root) {
      case 11: cm = (1ull<<11)|(1ull<<13)|(1ull<<16); break;
      case 21: cm = (1ull<<14)|(1ull<<15)|(1ull<<21)|(1ull<<22)|(1ull<<23); break;
      case 31: cm = (1ull<<15)|(1ull<<31)|(1ull<<32)|(1ull<<33); break;
      case 41: cm = (1ull<<41)|(1ull<<42)|(1ull<<43)|(1ull<<44); break;
      case 51: cm = (1ull<<15)|(1ull<<51)|(1ull<<52)|(1ull<<53); break;
      default: break;
    }
    s_cmask = cm;
  }
  __syncthreads();

  // ---- per-window metrics (thread w handles window w, w < 241) ----
  int myeq = (ftok[tid] == s_atok) ? 1 : 0;

  float sims = -1e30f, rootp = 0.f, regime = 0.f, ssum = 0.f;
  int c06 = 0;
  if (tid < WW) {
    const int root = s_root;
    const unsigned long long cmask = s_cmask;
    float exact = 0.f, positional = 0.f;
    unsigned long long wmask = 0ull;
    int c_rp = 0, c_al = 0, c_hd = 0;
#pragma unroll
    for (int s = 0; s < SP; s++) {
      int t = ftok[tid + s];
      wmask |= (1ull << t);
      if (t == sp_[s]) { exact += 1.f; positional += (1.0f - 0.04f * (float)s); }
      c_rp += (t == root);
      c_al += ((int)s_alias[t] == root);
      c_hd += (int)((cmask >> t) & 1ull);
    }
    exact *= (1.f / 16.f);
    positional *= (1.f / 11.2f);  // pos_w = linspace(1,0.4,16)/11.2
    float overlap = (float)__popcll(wmask & s_spanmask) * s_invden;
    rootp = (float)c_rp * (1.f / 16.f);
    float aliasc = (float)c_al * (1.f / 16.f);
    float hard   = (float)c_hd * (1.f / 16.f);
    regime = s_has ? (0.55f * hard  + 0.2f * overlap + 0.15f * aliasc + 0.1f  * rootp)
                   : (0.45f * exact + 0.3f * overlap + 0.1f  * aliasc + 0.15f * rootp);
    float sv = 0.25f * exact + 0.15f * overlap + 0.35f * positional + 0.25f * regime;
    sims = sv; ssum = sv;
    c06 = (sv >= 0.6f) ? 1 : 0;
  }

  // ---- final reductions over windows + token_c ----
  float msims = sims, srp = rootp, srg = regime, sss = ssum;
  int ceq = myeq, c6 = c06;
#pragma unroll
  for (int o = 16; o; o >>= 1) {
    msims = fmaxf(msims, __shfl_xor_sync(0xffffffffu, msims, o));
    srp += __shfl_xor_sync(0xffffffffu, srp, o);
    srg += __shfl_xor_sync(0xffffffffu, srg, o);
    sss += __shfl_xor_sync(0xffffffffu, sss, o);
    ceq += __shfl_xor_sync(0xffffffffu, ceq, o);
    c6  += __shfl_xor_sync(0xffffffffu, c6, o);
  }
  if (lane == 0) {
    sred[wp]      = msims;
    sred[8 + wp]  = srp;
    sred[16 + wp] = srg;
    sred[24 + wp] = sss;
    sred[32 + wp] = (float)ceq;
    sred[40 + wp] = (float)c6;
  }
  __syncthreads();

  if (tid == 0) {
    float best = -1e30f, trp = 0.f, trg = 0.f, tss = 0.f, teq = 0.f, t6 = 0.f;
    for (int k = 0; k < 8; k++) {
      best = fmaxf(best, sred[k]);
      trp += sred[8 + k]; trg += sred[16 + k]; tss += sred[24 + k];
      teq += sred[32 + k]; t6 += sred[40 + k];
    }
    const float eps = 1e-8f;
    float nr = fmaxf(sqrtf(s_nr2), eps);
    float nf = fmaxf(sqrtf(s_nf2) * (1.f / HH), eps);
    float sim = (s_dot * (1.f / HH)) / (nr * nf);
    float hidden_c = fmaxf(0.f, (1.f - sim) * 0.5f);
    float token_c = 1.f - teq * (1.f / HH);
    const float invW = 1.f / (float)WW;
    float mrp = trp * invW, mrc = trg * invW;
    float dmass = t6 * invW;
    float dcoh = 0.6f * (tss * invW) + 0.25f * mrp + 0.15f * mrc;
    float pattern_c = 1.f - (0.6f * best + 0.2f * mrp + 0.2f * mrc);
    float contr = fminf(1.f, fmaxf(0.f, 0.2f * hidden_c + 0.2f * token_c + 0.6f * pattern_c));

    out[0 * NPAIR + p] = contr;
    out[1 * NPAIR + p] = s_shift;
    out[2 * NPAIR + p] = sim;
    out[3 * NPAIR + p] = hidden_c;
    out[4 * NPAIR + p] = token_c;
    out[5 * NPAIR + p] = pattern_c;
    out[6 * NPAIR + p] = dmass;
    out[7 * NPAIR + p] = dcoh;
  }
}

extern "C" void kernel_launch(void* const* d_in, const int* in_sizes, int n_in,
                              void* d_out, int out_size) {
  (void)in_sizes; (void)n_in; (void)out_size;
  const float* hidden = (const float*)d_in[0];
  const float* anchor = (const float*)d_in[1];
  const int*   ids    = (const int*)d_in[2];
  const int*   aendp  = (const int*)d_in[3];
  cm_kernel<<<NPAIR, NT>>>(hidden, anchor, ids, aendp, (float*)d_out);
}

// round 3
// speedup vs baseline: 1.2000x; 1.2000x over previous
#include <cuda_runtime.h>

// Problem constants (fixed by setup_inputs: B=8,T=4096,D=1024,A=32,S=16,TTL=64)
#define NB_B 8
#define NB_T 4096
#define NB_D 1024
#define NB_A 32
#define SP   16
#define HH   256           // H = max(ttl*4, span*4)
#define WW   (HH - SP + 1) // 241
#define NPAIR (NB_B * NB_A)
#define CH   4             // chunks (CTAs) per pair in the streaming kernel
#define RB   (HH / CH)     // 64 rows per streaming CTA
#define NG   (NB_D / 4)    // 256 float4 column-groups

// scratch: per-chunk column-sum partials + row-norm (shift) partials
__device__ float4 g_cols[NPAIR * CH * NG];   // 4 MB
__device__ float  g_shift[NPAIR * CH];

__constant__ signed char c_alias[64] = {
  -1,-1,-1,-1,-1,-1,-1,-1,-1,-1,-1,
  11,-1,11,-1,-1,11,
  -1,-1,-1,-1,
  21,21,21,
  -1,-1,-1,-1,-1,-1,-1,
  31,31,31,
  -1,-1,-1,-1,-1,-1,-1,
  41,41,41,41,
  -1,-1,-1,-1,-1,-1,
  51,51,51,
  -1,-1,-1,-1,-1,-1,-1,-1,-1,-1
};

// ---------------- Kernel 1: stream 64 rows x 1024 cols per CTA ----------------
__global__ void __launch_bounds__(256, 2) cm_stream(
    const float* __restrict__ hidden,
    const float* __restrict__ anchor,
    const int*   __restrict__ aend)
{
  const int blk   = blockIdx.x;
  const int p     = blk >> 2;          // pair
  const int chunk = blk & 3;
  const int b     = p / NB_A;
  const int tid   = threadIdx.x;
  const int lane  = tid & 31;
  const int wp    = tid >> 5;          // 8 warps

  const int ae    = aend[p];
  const int start = ae + 1 + chunk * RB;

  const float4* __restrict__ hb =
      reinterpret_cast<const float4*>(hidden) + ((size_t)b * NB_T + start) * NG;
  const float4* __restrict__ af =
      reinterpret_cast<const float4*>(anchor) + (size_t)p * NG;

  // lane owns column-groups {i*32 + lane : i=0..7}
  float4 a[8], cs[8];
#pragma unroll
  for (int i = 0; i < 8; i++) {
    a[i] = af[i * 32 + lane];
    cs[i] = make_float4(0.f, 0.f, 0.f, 0.f);
  }

  float shift = 0.f;
  const int row0 = wp * (RB / 8);      // 8 rows per warp

#pragma unroll 1
  for (int r = 0; r < RB / 8; r++) {
    const float4* __restrict__ rp = hb + (size_t)(row0 + r) * NG;
    float4 x[8];
#pragma unroll
    for (int i = 0; i < 8; i++) x[i] = rp[i * 32 + lane];
    float v = 0.f;
#pragma unroll
    for (int i = 0; i < 8; i++) {
      cs[i].x += x[i].x; cs[i].y += x[i].y; cs[i].z += x[i].z; cs[i].w += x[i].w;
      float dx = x[i].x - a[i].x, dy = x[i].y - a[i].y;
      float dz = x[i].z - a[i].z, dw = x[i].w - a[i].w;
      v += dx * dx + dy * dy + dz * dz + dw * dw;
    }
#pragma unroll
    for (int o = 16; o; o >>= 1) v += __shfl_xor_sync(0xffffffffu, v, o);
    shift += sqrtf(v);   // identical value in all lanes (xor-bfly reduce)
  }

  // combine 8 warps' column sums via smem, write block partial to scratch
  __shared__ float4 scs[8 * NG];   // 32 KB
  __shared__ float  ssh[8];
#pragma unroll
  for (int i = 0; i < 8; i++) scs[wp * NG + i * 32 + lane] = cs[i];
  if (lane == 0) ssh[wp] = shift;
  __syncthreads();

  float4 t = scs[tid];
#pragma unroll
  for (int w = 1; w < 8; w++) {
    float4 u = scs[w * NG + tid];
    t.x += u.x; t.y += u.y; t.z += u.z; t.w += u.w;
  }
  g_cols[(size_t)blk * NG + tid] = t;
  if (tid == 0) {
    float s = 0.f;
#pragma unroll
    for (int k = 0; k < 8; k++) s += ssh[k];
    g_shift[blk] = s;
  }
}

// ---------------- Kernel 2: combine partials + token-window phase ----------------
__global__ void __launch_bounds__(256, 4) cm_final(
    const float* __restrict__ anchor,
    const int*   __restrict__ ids,
    const int*   __restrict__ aend,
    float*       __restrict__ out)
{
  const int p    = blockIdx.x;
  const int b    = p / NB_A;
  const int tid  = threadIdx.x;
  const int lane = tid & 31;
  const int wp   = tid >> 5;

  __shared__ float sred[48];
  __shared__ int   ftok[HH];
  __shared__ int   sp_[SP];
  __shared__ signed char s_alias[64];
  __shared__ int   s_root, s_has, s_atok;
  __shared__ float s_invden;
  __shared__ unsigned long long s_spanmask, s_cmask;
  __shared__ float s_shift, s_dot, s_nf2, s_nr2;

  const int ae    = aend[p];
  const int start = ae + 1;

  if (tid < 64) s_alias[tid] = c_alias[tid];
  ftok[tid] = ids[b * NB_T + start + tid];
  if (tid < SP) sp_[tid] = ids[b * NB_T + ae - (SP - 1) + tid];
  if (tid == 0) s_atok = ids[b * NB_T + ae];

  // combine column-sum partials; thread tid owns column-group tid
  const float4 a4 = reinterpret_cast<const float4*>(anchor)[(size_t)p * NG + tid];
  float4 cs = g_cols[(size_t)(p * CH + 0) * NG + tid];
#pragma unroll
  for (int c = 1; c < CH; c++) {
    float4 u = g_cols[(size_t)(p * CH + c) * NG + tid];
    cs.x += u.x; cs.y += u.y; cs.z += u.z; cs.w += u.w;
  }

  float dot = a4.x * cs.x + a4.y * cs.y + a4.z * cs.z + a4.w * cs.w;
  float nf2 = cs.x * cs.x + cs.y * cs.y + cs.z * cs.z + cs.w * cs.w;
  float nr2 = a4.x * a4.x + a4.y * a4.y + a4.z * a4.z + a4.w * a4.w;
#pragma unroll
  for (int o = 16; o; o >>= 1) {
    dot += __shfl_xor_sync(0xffffffffu, dot, o);
    nf2 += __shfl_xor_sync(0xffffffffu, nf2, o);
    nr2 += __shfl_xor_sync(0xffffffffu, nr2, o);
  }
  if (lane == 0) { sred[8 + wp] = dot; sred[16 + wp] = nf2; sred[24 + wp] = nr2; }
  __syncthreads();

  if (tid == 0) {
    float d = 0.f, f = 0.f, r2 = 0.f;
    for (int k = 0; k < 8; k++) { d += sred[8 + k]; f += sred[16 + k]; r2 += sred[24 + k]; }
    float sh = 0.f;
#pragma unroll
    for (int c = 0; c < CH; c++) sh += g_shift[p * CH + c];
    s_shift = sh * (1.f / HH);
    s_dot = d; s_nf2 = f; s_nr2 = r2;

    // root / span analysis
    int root = -1;
    for (int s = 0; s < SP; s++) {
      int al = s_alias[sp_[s]];
      if (al >= 0) { root = al; break; }
    }
    if (root < 0) {
      int counts[SP]; int maxc = 0;
      for (int s = 0; s < SP; s++) {
        int c2 = 0;
        for (int s2 = 0; s2 < SP; s2++) c2 += (sp_[s2] == sp_[s]);
        counts[s] = c2; if (c2 > maxc) maxc = c2;
      }
      int mode = 64;
      for (int s = 0; s < SP; s++)
        if (counts[s] == maxc && sp_[s] < mode) mode = sp_[s];
      root = mode;
    }
    unsigned long long smask = 0ull; int den = 0;
    for (int s = 0; s < SP; s++) {
      bool first = true;
      for (int s2 = 0; s2 < s; s2++)
        if (sp_[s2] == sp_[s]) { first = false; break; }
      if (first) { den++; smask |= (1ull << sp_[s]); }
    }
    s_root = root;
    s_spanmask = smask;
    s_invden = 1.f / (float)den;
    s_has = (root == 11 || root == 21 || root == 31 || root == 41 || root == 51) ? 1 : 0;
    unsigned long long cm = 0ull;
    switch (root) {
      case 11: cm = (1ull<<11)|(1ull<<13)|(1ull<<16); break;
      case 21: cm = (1ull<<14)|(1ull<<15)|(1ull<<21)|(1ull<<22)|(1ull<<23); break;
      case 31: cm = (1ull<<15)|(1ull<<31)|(1ull<<32)|(1ull<<33); break;
      case 41: cm = (1ull<<41)|(1ull<<42)|(1ull<<43)|(1ull<<44); break;
      case 51: cm = (1ull<<15)|(1ull<<51)|(1ull<<52)|(1ull<<53); break;
      default: break;
    }
    s_cmask = cm;
  }
  __syncthreads();

  // per-window metrics (thread w handles window w, w < 241)
  int myeq = (ftok[tid] == s_atok) ? 1 : 0;

  float sims = -1e30f, rootp = 0.f, regime = 0.f, ssum = 0.f;
  int c06 = 0;
  if (tid < WW) {
    const int root = s_root;
    const unsigned long long cmask = s_cmask;
    float exact = 0.f, positional = 0.f;
    unsigned long long wmask = 0ull;
    int c_rp = 0, c_al = 0, c_hd = 0;
#pragma unroll
    for (int s = 0; s < SP; s++) {
      int t = ftok[tid + s];
      wmask |= (1ull << t);
      if (t == sp_[s]) { exact += 1.f; positional += (1.0f - 0.04f * (float)s); }
      c_rp += (t == root);
      c_al += ((int)s_alias[t] == root);
      c_hd += (int)((cmask >> t) & 1ull);
    }
    exact *= (1.f / 16.f);
    positional *= (1.f / 11.2f);
    float overlap = (float)__popcll(wmask & s_spanmask) * s_invden;
    rootp = (float)c_rp * (1.f / 16.f);
    float aliasc = (float)c_al * (1.f / 16.f);
    float hard   = (float)c_hd * (1.f / 16.f);
    regime = s_has ? (0.55f * hard  + 0.2f * overlap + 0.15f * aliasc + 0.1f  * rootp)
                   : (0.45f * exact + 0.3f * overlap + 0.1f  * aliasc + 0.15f * rootp);
    float sv = 0.25f * exact + 0.15f * overlap + 0.35f * positional + 0.25f * regime;
    sims = sv; ssum = sv;
    c06 = (sv >= 0.6f) ? 1 : 0;
  }

  float msims = sims, srp = rootp, srg = regime, sss = ssum;
  int ceq = myeq, c6 = c06;
#pragma unroll
  for (int o = 16; o; o >>= 1) {
    msims = fmaxf(msims, __shfl_xor_sync(0xffffffffu, msims, o));
    srp += __shfl_xor_sync(0xffffffffu, srp, o);
    srg += __shfl_xor_sync(0xffffffffu, srg, o);
    sss += __shfl_xor_sync(0xffffffffu, sss, o);
    ceq += __shfl_xor_sync(0xffffffffu, ceq, o);
    c6  += __shfl_xor_sync(0xffffffffu, c6, o);
  }
  if (lane == 0) {
    sred[wp]      = msims;
    sred[8 + wp]  = srp;
    sred[16 + wp] = srg;
    sred[24 + wp] = sss;
    sred[32 + wp] = (float)ceq;
    sred[40 + wp] = (float)c6;
  }
  __syncthreads();

  if (tid == 0) {
    float best = -1e30f, trp = 0.f, trg = 0.f, tss = 0.f, teq = 0.f, t6 = 0.f;
    for (int k = 0; k < 8; k++) {
      best = fmaxf(best, sred[k]);
      trp += sred[8 + k]; trg += sred[16 + k]; tss += sred[24 + k];
      teq += sred[32 + k]; t6 += sred[40 + k];
    }
    const float eps = 1e-8f;
    float nr = fmaxf(sqrtf(s_nr2), eps);
    float nf = fmaxf(sqrtf(s_nf2) * (1.f / HH), eps);
    float sim = (s_dot * (1.f / HH)) / (nr * nf);
    float hidden_c = fmaxf(0.f, (1.f - sim) * 0.5f);
    float token_c = 1.f - teq * (1.f / HH);
    const float invW = 1.f / (float)WW;
    float mrp = trp * invW, mrc = trg * invW;
    float dmass = t6 * invW;
    float dcoh = 0.6f * (tss * invW) + 0.25f * mrp + 0.15f * mrc;
    float pattern_c = 1.f - (0.6f * best + 0.2f * mrp + 0.2f * mrc);
    float contr = fminf(1.f, fmaxf(0.f, 0.2f * hidden_c + 0.2f * token_c + 0.6f * pattern_c));

    out[0 * NPAIR + p] = contr;
    out[1 * NPAIR + p] = s_shift;
    out[2 * NPAIR + p] = sim;
    out[3 * NPAIR + p] = hidden_c;
    out[4 * NPAIR + p] = token_c;
    out[5 * NPAIR + p] = pattern_c;
    out[6 * NPAIR + p] = dmass;
    out[7 * NPAIR + p] = dcoh;
  }
}

extern "C" void kernel_launch(void* const* d_in, const int* in_sizes, int n_in,
                              void* d_out, int out_size) {
  (void)in_sizes; (void)n_in; (void)out_size;
  const float* hidden = (const float*)d_in[0];
  const float* anchor = (const float*)d_in[1];
  const int*   ids    = (const int*)d_in[2];
  const int*   aendp  = (const int*)d_in[3];
  cm_stream<<<NPAIR * CH, 256>>>(hidden, anchor, aendp);
  cm_final <<<NPAIR, 256>>>(anchor, ids, aendp, (float*)d_out);
}

// round 4
// speedup vs baseline: 1.2850x; 1.0708x over previous
#include <cuda_runtime.h>

// Problem constants (fixed by setup_inputs: B=8,T=4096,D=1024,A=32,S=16,TTL=64)
#define NB_B 8
#define NB_T 4096
#define NB_D 1024
#define NB_A 32
#define SP   16
#define HH   256           // H = max(ttl*4, span*4)
#define WW   (HH - SP + 1) // 241
#define NPAIR (NB_B * NB_A)
#define CH   4             // column chunks (CTAs) per pair
#define CG   64            // float4 groups per chunk (256 floats)
#define NG   (NB_D / 4)    // 256 float4 groups per row

// scratch: per-(pair,row) 4 chunk partial row-norms^2  (1 MB), + 3 scalars per chunk
__device__ float g_rshift[NPAIR * HH * CH];
__device__ float g_dot[NPAIR * CH];
__device__ float g_nf2[NPAIR * CH];
__device__ float g_nr2[NPAIR * CH];

__constant__ signed char c_alias[64] = {
  -1,-1,-1,-1,-1,-1,-1,-1,-1,-1,-1,
  11,-1,11,-1,-1,11,
  -1,-1,-1,-1,
  21,21,21,
  -1,-1,-1,-1,-1,-1,-1,
  31,31,31,
  -1,-1,-1,-1,-1,-1,-1,
  41,41,41,41,
  -1,-1,-1,-1,-1,-1,
  51,51,51,
  -1,-1,-1,-1,-1,-1,-1,-1,-1,-1
};

// ------- Kernel 1: each CTA streams ALL 256 rows of a 256-column slice -------
__global__ void __launch_bounds__(256, 3) cm_stream(
    const float* __restrict__ hidden,
    const float* __restrict__ anchor,
    const int*   __restrict__ aend)
{
  const int blk   = blockIdx.x;
  const int p     = blk >> 2;          // pair
  const int chunk = blk & 3;           // column chunk
  const int b     = p / NB_A;
  const int tid   = threadIdx.x;
  const int lane  = tid & 31;
  const int wp    = tid >> 5;          // 8 warps; warp w owns rows [w*32, w*32+32)

  const int ae    = aend[p];
  const int start = ae + 1;

  const float4* __restrict__ hb =
      reinterpret_cast<const float4*>(hidden)
      + ((size_t)b * NB_T + start) * NG + chunk * CG;
  const float4* __restrict__ af =
      reinterpret_cast<const float4*>(anchor) + (size_t)p * NG + chunk * CG;

  // lane owns groups lane and lane+32 of this chunk
  const float4 a0 = af[lane];
  const float4 a1 = af[lane + 32];
  float4 cs0 = make_float4(0.f,0.f,0.f,0.f);
  float4 cs1 = make_float4(0.f,0.f,0.f,0.f);

  const int row0 = wp * 32;
  float* __restrict__ rsh = g_rshift + ((size_t)p * HH) * CH + chunk;

#pragma unroll 1
  for (int it = 0; it < 8; it++) {
    const int r = row0 + it * 4;
    float4 x[4], y[4];
#pragma unroll
    for (int j = 0; j < 4; j++) {
      x[j] = hb[(size_t)(r + j) * NG + lane];
      y[j] = hb[(size_t)(r + j) * NG + lane + 32];
    }
    float v[4];
#pragma unroll
    for (int j = 0; j < 4; j++) {
      cs0.x += x[j].x; cs0.y += x[j].y; cs0.z += x[j].z; cs0.w += x[j].w;
      cs1.x += y[j].x; cs1.y += y[j].y; cs1.z += y[j].z; cs1.w += y[j].w;
      float dx = x[j].x - a0.x, dy = x[j].y - a0.y;
      float dz = x[j].z - a0.z, dw = x[j].w - a0.w;
      float ex = y[j].x - a1.x, ey = y[j].y - a1.y;
      float ez = y[j].z - a1.z, ew = y[j].w - a1.w;
      v[j] = dx*dx + dy*dy + dz*dz + dw*dw + ex*ex + ey*ey + ez*ez + ew*ew;
    }
#pragma unroll
    for (int j = 0; j < 4; j++) {
#pragma unroll
      for (int o = 16; o; o >>= 1) v[j] += __shfl_xor_sync(0xffffffffu, v[j], o);
    }
    if (lane == 0) {
      rsh[(r + 0) * CH] = v[0];
      rsh[(r + 1) * CH] = v[1];
      rsh[(r + 2) * CH] = v[2];
      rsh[(r + 3) * CH] = v[3];
    }
  }

  // combine warps' column sums -> chunk scalars: dot, nf2, nr2
  __shared__ float4 scs[8 * 64];      // 4 KB
  __shared__ float  sfin[3 * 8];
  scs[wp * 64 + lane]      = cs0;
  scs[wp * 64 + lane + 32] = cs1;
  __syncthreads();

  if (tid < 64) {
    float4 t = scs[tid];
#pragma unroll
    for (int w = 1; w < 8; w++) {
      float4 u = scs[w * 64 + tid];
      t.x += u.x; t.y += u.y; t.z += u.z; t.w += u.w;
    }
    float4 a = af[tid];
    float dot = a.x*t.x + a.y*t.y + a.z*t.z + a.w*t.w;
    float nf2 = t.x*t.x + t.y*t.y + t.z*t.z + t.w*t.w;
    float nr2 = a.x*a.x + a.y*a.y + a.z*a.z + a.w*a.w;
#pragma unroll
    for (int o = 16; o; o >>= 1) {
      dot += __shfl_xor_sync(0xffffffffu, dot, o);
      nf2 += __shfl_xor_sync(0xffffffffu, nf2, o);
      nr2 += __shfl_xor_sync(0xffffffffu, nr2, o);
    }
    if (lane == 0) {
      sfin[wp * 3 + 0] = dot; sfin[wp * 3 + 1] = nf2; sfin[wp * 3 + 2] = nr2;
    }
  }
  __syncthreads();
  if (tid == 0) {
    g_dot[blk] = sfin[0] + sfin[3];
    g_nf2[blk] = sfin[1] + sfin[4];
    g_nr2[blk] = sfin[2] + sfin[5];
  }
}

// ------- Kernel 2: combine scalars + row norms + token-window phase -------
__global__ void __launch_bounds__(256, 4) cm_final(
    const int*   __restrict__ ids,
    const int*   __restrict__ aend,
    float*       __restrict__ out)
{
  const int p    = blockIdx.x;
  const int b    = p / NB_A;
  const int tid  = threadIdx.x;
  const int lane = tid & 31;
  const int wp   = tid >> 5;

  __shared__ float sred[48];
  __shared__ int   ftok[HH];
  __shared__ int   sp_[SP];
  __shared__ signed char s_alias[64];
  __shared__ int   s_root, s_has, s_atok;
  __shared__ float s_invden;
  __shared__ unsigned long long s_spanmask, s_cmask;
  __shared__ float s_shift;

  const int ae    = aend[p];
  const int start = ae + 1;

  if (tid < 64) s_alias[tid] = c_alias[tid];
  ftok[tid] = ids[b * NB_T + start + tid];
  if (tid < SP) sp_[tid] = ids[b * NB_T + ae - (SP - 1) + tid];
  if (tid == 0) s_atok = ids[b * NB_T + ae];

  // per-row norm: thread tid owns row tid; read 4 chunk partials as one float4
  float4 rp4 = reinterpret_cast<const float4*>(g_rshift)[p * HH + tid];
  float rn = sqrtf(rp4.x + rp4.y + rp4.z + rp4.w);
#pragma unroll
  for (int o = 16; o; o >>= 1) rn += __shfl_xor_sync(0xffffffffu, rn, o);
  if (lane == 0) sred[40 + wp] = rn;
  __syncthreads();

  if (tid == 0) {
    float sh = 0.f;
#pragma unroll
    for (int k = 0; k < 8; k++) sh += sred[40 + k];
    s_shift = sh * (1.f / HH);

    // root / span analysis
    int root = -1;
    for (int s = 0; s < SP; s++) {
      int al = s_alias[sp_[s]];
      if (al >= 0) { root = al; break; }
    }
    if (root < 0) {
      int counts[SP]; int maxc = 0;
      for (int s = 0; s < SP; s++) {
        int c2 = 0;
        for (int s2 = 0; s2 < SP; s2++) c2 += (sp_[s2] == sp_[s]);
        counts[s] = c2; if (c2 > maxc) maxc = c2;
      }
      int mode = 64;
      for (int s = 0; s < SP; s++)
        if (counts[s] == maxc && sp_[s] < mode) mode = sp_[s];
      root = mode;
    }
    unsigned long long smask = 0ull; int den = 0;
    for (int s = 0; s < SP; s++) {
      bool first = true;
      for (int s2 = 0; s2 < s; s2++)
        if (sp_[s2] == sp_[s]) { first = false; break; }
      if (first) { den++; smask |= (1ull << sp_[s]); }
    }
    s_root = root;
    s_spanmask = smask;
    s_invden = 1.f / (float)den;
    s_has = (root == 11 || root == 21 || root == 31 || root == 41 || root == 51) ? 1 : 0;
    unsigned long long cm = 0ull;
    switch (root) {
      case 11: cm = (1ull<<11)|(1ull<<13)|(1ull<<16); break;
      case 21: cm = (1ull<<14)|(1ull<<15)|(1ull<<21)|(1ull<<22)|(1ull<<23); break;
      case 31: cm = (1ull<<15)|(1ull<<31)|(1ull<<32)|(1ull<<33); break;
      case 41: cm = (1ull<<41)|(1ull<<42)|(1ull<<43)|(1ull<<44); break;
      case 51: cm = (1ull<<15)|(1ull<<51)|(1ull<<52)|(1ull<<53); break;
      default: break;
    }
    s_cmask = cm;
  }
  __syncthreads();

  // per-window metrics (thread w handles window w, w < 241)
  int myeq = (ftok[tid] == s_atok) ? 1 : 0;

  float sims = -1e30f, rootp = 0.f, regime = 0.f, ssum = 0.f;
  int c06 = 0;
  if (tid < WW) {
    const int root = s_root;
    const unsigned long long cmask = s_cmask;
    float exact = 0.f, positional = 0.f;
    unsigned long long wmask = 0ull;
    int c_rp = 0, c_al = 0, c_hd = 0;
#pragma unroll
    for (int s = 0; s < SP; s++) {
      int t = ftok[tid + s];
      wmask |= (1ull << t);
      if (t == sp_[s]) { exact += 1.f; positional += (1.0f - 0.04f * (float)s); }
      c_rp += (t == root);
      c_al += ((int)s_alias[t] == root);
      c_hd += (int)((cmask >> t) & 1ull);
    }
    exact *= (1.f / 16.f);
    positional *= (1.f / 11.2f);
    float overlap = (float)__popcll(wmask & s_spanmask) * s_invden;
    rootp = (float)c_rp * (1.f / 16.f);
    float aliasc = (float)c_al * (1.f / 16.f);
    float hard   = (float)c_hd * (1.f / 16.f);
    regime = s_has ? (0.55f * hard  + 0.2f * overlap + 0.15f * aliasc + 0.1f  * rootp)
                   : (0.45f * exact + 0.3f * overlap + 0.1f  * aliasc + 0.15f * rootp);
    float sv = 0.25f * exact + 0.15f * overlap + 0.35f * positional + 0.25f * regime;
    sims = sv; ssum = sv;
    c06 = (sv >= 0.6f) ? 1 : 0;
  }

  float msims = sims, srp = rootp, srg = regime, sss = ssum;
  int ceq = myeq, c6 = c06;
#pragma unroll
  for (int o = 16; o; o >>= 1) {
    msims = fmaxf(msims, __shfl_xor_sync(0xffffffffu, msims, o));
    srp += __shfl_xor_sync(0xffffffffu, srp, o);
    srg += __shfl_xor_sync(0xffffffffu, srg, o);
    sss += __shfl_xor_sync(0xffffffffu, sss, o);
    ceq += __shfl_xor_sync(0xffffffffu, ceq, o);
    c6  += __shfl_xor_sync(0xffffffffu, c6, o);
  }
  if (lane == 0) {
    sred[wp]      = msims;
    sred[8 + wp]  = srp;
    sred[16 + wp] = srg;
    sred[24 + wp] = sss;
    sred[32 + wp] = (float)ceq;
    sred[40 + wp] = (float)c6;    // row-norm slot no longer needed
  }
  __syncthreads();

  if (tid == 0) {
    float best = -1e30f, trp = 0.f, trg = 0.f, tss = 0.f, teq = 0.f, t6 = 0.f;
    for (int k = 0; k < 8; k++) {
      best = fmaxf(best, sred[k]);
      trp += sred[8 + k]; trg += sred[16 + k]; tss += sred[24 + k];
      teq += sred[32 + k]; t6 += sred[40 + k];
    }
    float dot = 0.f, nf2 = 0.f, nr2 = 0.f;
#pragma unroll
    for (int c = 0; c < CH; c++) {
      dot += g_dot[p * CH + c];
      nf2 += g_nf2[p * CH + c];
      nr2 += g_nr2[p * CH + c];
    }
    const float eps = 1e-8f;
    float nr = fmaxf(sqrtf(nr2), eps);
    float nf = fmaxf(sqrtf(nf2) * (1.f / HH), eps);
    float sim = (dot * (1.f / HH)) / (nr * nf);
    float hidden_c = fmaxf(0.f, (1.f - sim) * 0.5f);
    float token_c = 1.f - teq * (1.f / HH);
    const float invW = 1.f / (float)WW;
    float mrp = trp * invW, mrc = trg * invW;
    float dmass = t6 * invW;
    float dcoh = 0.6f * (tss * invW) + 0.25f * mrp + 0.15f * mrc;
    float pattern_c = 1.f - (0.6f * best + 0.2f * mrp + 0.2f * mrc);
    float contr = fminf(1.f, fmaxf(0.f, 0.2f * hidden_c + 0.2f * token_c + 0.6f * pattern_c));

    out[0 * NPAIR + p] = contr;
    out[1 * NPAIR + p] = s_shift;
    out[2 * NPAIR + p] = sim;
    out[3 * NPAIR + p] = hidden_c;
    out[4 * NPAIR + p] = token_c;
    out[5 * NPAIR + p] = pattern_c;
    out[6 * NPAIR + p] = dmass;
    out[7 * NPAIR + p] = dcoh;
  }
}

extern "C" void kernel_launch(void* const* d_in, const int* in_sizes, int n_in,
                              void* d_out, int out_size) {
  (void)in_sizes; (void)n_in; (void)out_size;
  const float* hidden = (const float*)d_in[0];
  const float* anchor = (const float*)d_in[1];
  const int*   ids    = (const int*)d_in[2];
  const int*   aendp  = (const int*)d_in[3];
  cm_stream<<<NPAIR * CH, 256>>>(hidden, anchor, aendp);
  cm_final <<<NPAIR, 256>>>(ids, aendp, (float*)d_out);
}